// round 13
// baseline (speedup 1.0000x reference)
#include <cuda_runtime.h>
#include <cuda_fp16.h>
#include <math.h>

#define NN 100000
#define EE 3200000
#define BKT 128                  // bucket capacity per node (P(overflow) ~ 1e-30)

typedef unsigned long long ull_t;

// ---- static device scratch (no dynamic allocation allowed) ----
__device__ int    g_cnt[NN];                 // cursor, ends as degree (incl self-loop)
__device__ int    g_bkt[(size_t)NN * BKT];   // column indices, 512B-aligned rows
__device__ __half g_xwh[(size_t)NN * 64];    // UNscaled fp16 gather table, layer1
__device__ float  g_h1[(size_t)NN * 64];
__device__ __half g_t2h[(size_t)NN * 32];    // dinv-scaled fp16 gather table, layer2
__device__ float  g_t3[(size_t)NN * 2];      // dinv-scaled layer3 pre-agg (fp32)

// ---- packed f32x2 helpers (two independent fp32 FMAs) ----
__device__ __forceinline__ void ffma2(ull_t& acc, ull_t a, ull_t b) {
    asm("fma.rn.f32x2 %0, %1, %2, %0;" : "+l"(acc) : "l"(a), "l"(b));
}
__device__ __forceinline__ ull_t fdup(float v) {
    ull_t d;
    asm("mov.b64 %0, {%1, %1};" : "=l"(d) : "f"(v));
    return d;
}
__device__ __forceinline__ float2 funpack(ull_t v) {
    float2 r;
    asm("mov.b64 {%0, %1}, %2;" : "=f"(r.x), "=f"(r.y) : "l"(v));
    return r;
}
__device__ __forceinline__ __half2 shflx_h2(__half2 v, int off) {
    unsigned u = *(unsigned*)&v;
    u = __shfl_xor_sync(0xffffffffu, u, off);
    return *(__half2*)&u;
}
__device__ __forceinline__ __half2 u2h2(unsigned u) { return *(__half2*)&u; }

// ---------------- bucket CSR build (single atomic pass) ----------------

__global__ void k_initbkt() {
    int i = blockIdx.x * blockDim.x + threadIdx.x;
    if (i >= NN) return;
    g_cnt[i] = 1;
    g_bkt[(size_t)i * BKT] = i;   // self-loop at slot 0
}

// 4 edges per thread, int4 src/dst reads (EE % 4 == 0)
__global__ void k_scatter(const int* __restrict__ ei) {
    int t = blockIdx.x * blockDim.x + threadIdx.x;
    if (t >= EE / 4) return;
    int4 s = ((const int4*)ei)[t];
    int4 d = ((const int4*)(ei + EE))[t];
    int p0 = atomicAdd(&g_cnt[d.x], 1);
    if (p0 < BKT) g_bkt[(size_t)d.x * BKT + p0] = s.x;
    int p1 = atomicAdd(&g_cnt[d.y], 1);
    if (p1 < BKT) g_bkt[(size_t)d.y * BKT + p1] = s.y;
    int p2 = atomicAdd(&g_cnt[d.z], 1);
    if (p2 < BKT) g_bkt[(size_t)d.z * BKT + p2] = s.z;
    int p3 = atomicAdd(&g_cnt[d.w], 1);
    if (p3 < BKT) g_bkt[(size_t)d.w * BKT + p3] = s.w;
}

// ---------------- dense GEMMs (f32x2 packed FFMA) ----------------

// x[NN,128] @ W1[128,64] -> g_xwh (fp16, UNscaled); 32 rows/block
__global__ void k_gemm1(const float* __restrict__ x, const float* __restrict__ W) {
    __shared__ float Ws[128 * 64];     // 32 KB
    __shared__ ull_t xd[32][128];      // 32 KB: duplicated {x,x}
    int tid = threadIdx.x;
    for (int i = tid; i < 2048; i += 256)
        ((float4*)Ws)[i] = ((const float4*)W)[i];
    int row0 = blockIdx.x * 32;
    for (int i = tid; i < 1024; i += 256) {
        int r = i >> 5, c = i & 31;
        float4 v = ((const float4*)(x + (size_t)(row0 + r) * 128))[c];
        xd[r][c * 4 + 0] = fdup(v.x);
        xd[r][c * 4 + 1] = fdup(v.y);
        xd[r][c * 4 + 2] = fdup(v.z);
        xd[r][c * 4 + 3] = fdup(v.w);
    }
    __syncthreads();
    int tx = tid & 15, ty = tid >> 4;
    ull_t a00 = 0, a01 = 0, a10 = 0, a11 = 0;
#pragma unroll 8
    for (int k = 0; k < 128; k++) {
        ulonglong2 w = ((const ulonglong2*)(Ws + k * 64))[tx];
        ull_t xa = xd[ty][k], xb = xd[ty + 16][k];
        ffma2(a00, xa, w.x); ffma2(a01, xa, w.y);
        ffma2(a10, xb, w.x); ffma2(a11, xb, w.y);
    }
    {
        float2 p0 = funpack(a00), p1 = funpack(a01);
        __half2 h0 = __floats2half2_rn(p0.x, p0.y);
        __half2 h1 = __floats2half2_rn(p1.x, p1.y);
        uint2 u; u.x = *(unsigned*)&h0; u.y = *(unsigned*)&h1;
        *(uint2*)(g_xwh + (size_t)(row0 + ty) * 64 + tx * 4) = u;
    }
    {
        float2 p0 = funpack(a10), p1 = funpack(a11);
        __half2 h0 = __floats2half2_rn(p0.x, p0.y);
        __half2 h1 = __floats2half2_rn(p1.x, p1.y);
        uint2 u; u.x = *(unsigned*)&h0; u.y = *(unsigned*)&h1;
        *(uint2*)(g_xwh + (size_t)(row0 + ty + 16) * 64 + tx * 4) = u;
    }
}

// g_h1[NN,64] @ W2[64,32] * dinv[row] -> g_t2h (fp16) ; 64 rows/block
__global__ void k_gemm2(const float* __restrict__ W) {
    __shared__ float Ws[64 * 32];
    __shared__ ull_t xd[64][64];
    int tid = threadIdx.x;
    for (int i = tid; i < 512; i += 256)
        ((float4*)Ws)[i] = ((const float4*)W)[i];
    int row0 = blockIdx.x * 64;
    for (int i = tid; i < 1024; i += 256) {
        int r = i >> 4, c = i & 15;
        int gr = row0 + r;
        float4 v = (gr < NN) ? ((const float4*)(g_h1 + (size_t)gr * 64))[c]
                             : make_float4(0, 0, 0, 0);
        xd[r][c * 4 + 0] = fdup(v.x);
        xd[r][c * 4 + 1] = fdup(v.y);
        xd[r][c * 4 + 2] = fdup(v.z);
        xd[r][c * 4 + 3] = fdup(v.w);
    }
    __syncthreads();
    int tx = tid & 7, ty = tid >> 3;
    ull_t a00 = 0, a01 = 0, a10 = 0, a11 = 0;
#pragma unroll 8
    for (int k = 0; k < 64; k++) {
        ulonglong2 w = ((const ulonglong2*)(Ws + k * 32))[tx];
        ull_t xa = xd[ty][k], xb = xd[ty + 32][k];
        ffma2(a00, xa, w.x); ffma2(a01, xa, w.y);
        ffma2(a10, xb, w.x); ffma2(a11, xb, w.y);
    }
    int r0 = row0 + ty, r1 = row0 + ty + 32;
    if (r0 < NN) {
        float s = rsqrtf((float)g_cnt[r0]);
        float2 p0 = funpack(a00), p1 = funpack(a01);
        __half2 h0 = __floats2half2_rn(p0.x * s, p0.y * s);
        __half2 h1 = __floats2half2_rn(p1.x * s, p1.y * s);
        uint2 u; u.x = *(unsigned*)&h0; u.y = *(unsigned*)&h1;
        *(uint2*)(g_t2h + (size_t)r0 * 32 + tx * 4) = u;
    }
    if (r1 < NN) {
        float s = rsqrtf((float)g_cnt[r1]);
        float2 p0 = funpack(a10), p1 = funpack(a11);
        __half2 h0 = __floats2half2_rn(p0.x * s, p0.y * s);
        __half2 h1 = __floats2half2_rn(p1.x * s, p1.y * s);
        uint2 u; u.x = *(unsigned*)&h0; u.y = *(unsigned*)&h1;
        *(uint2*)(g_t2h + (size_t)r1 * 32 + tx * 4) = u;
    }
}

// ---------------- bucket aggregations (multi-edge, 2x unrolled chains) ----------------

// warp per node, 8 edges per unrolled iter: lane = group(2b)*8 + seg(3b)
__global__ void __launch_bounds__(256, 6) k_agg64(const float* __restrict__ b) {
    int node = (blockIdx.x * blockDim.x + threadIdx.x) >> 5;
    if (node >= NN) return;
    int lane = threadIdx.x & 31;
    int g = lane >> 3;       // edge group 0-3
    int seg = lane & 7;      // feature segment (8 features = 16B)
    int deg = g_cnt[node];
    const int* bp = g_bkt + (size_t)node * BKT;
    const __half* tab = g_xwh;
    __half2 a0 = __float2half2_rn(0.f), a1 = a0, a2 = a0, a3 = a0;
    for (int j = 0; j < deg; j += 8) {
        // hoist both index loads -> two independent gather chains in flight
        int e0 = j + g, e1 = j + 4 + g;
        bool q0 = e0 < deg, q1 = e1 < deg;
        int c0 = __ldg(bp + min(e0, deg - 1));
        int c1 = __ldg(bp + min(e1, deg - 1));
        float w0f = q0 ? rsqrtf((float)__ldg(&g_cnt[c0])) : 0.f;
        float w1f = q1 ? rsqrtf((float)__ldg(&g_cnt[c1])) : 0.f;
        uint4 va = *(const uint4*)(tab + (size_t)c0 * 64 + seg * 8);
        uint4 vb = *(const uint4*)(tab + (size_t)c1 * 64 + seg * 8);
        __half2 w0 = __float2half2_rn(w0f);
        __half2 w1 = __float2half2_rn(w1f);
        a0 = __hfma2(w0, u2h2(va.x), a0);
        a1 = __hfma2(w0, u2h2(va.y), a1);
        a2 = __hfma2(w0, u2h2(va.z), a2);
        a3 = __hfma2(w0, u2h2(va.w), a3);
        a0 = __hfma2(w1, u2h2(vb.x), a0);
        a1 = __hfma2(w1, u2h2(vb.y), a1);
        a2 = __hfma2(w1, u2h2(vb.z), a2);
        a3 = __hfma2(w1, u2h2(vb.w), a3);
    }
    // reduce across the 4 edge groups (lanes xor 8, 16)
#pragma unroll
    for (int off = 8; off <= 16; off <<= 1) {
        a0 = __hadd2(a0, shflx_h2(a0, off));
        a1 = __hadd2(a1, shflx_h2(a1, off));
        a2 = __hadd2(a2, shflx_h2(a2, off));
        a3 = __hadd2(a3, shflx_h2(a3, off));
    }
    if (lane < 8) {     // seg == lane
        float s = rsqrtf((float)deg);
        float2 f0 = __half22float2(a0), f1 = __half22float2(a1);
        float2 f2 = __half22float2(a2), f3 = __half22float2(a3);
        float4 b0 = __ldg((const float4*)(b + seg * 8));
        float4 b4 = __ldg((const float4*)(b + seg * 8 + 4));
        float4 o0, o1;
        o0.x = fmaxf(fmaf(f0.x, s, b0.x), 0.f);
        o0.y = fmaxf(fmaf(f0.y, s, b0.y), 0.f);
        o0.z = fmaxf(fmaf(f1.x, s, b0.z), 0.f);
        o0.w = fmaxf(fmaf(f1.y, s, b0.w), 0.f);
        o1.x = fmaxf(fmaf(f2.x, s, b4.x), 0.f);
        o1.y = fmaxf(fmaf(f2.y, s, b4.y), 0.f);
        o1.z = fmaxf(fmaf(f3.x, s, b4.z), 0.f);
        o1.w = fmaxf(fmaf(f3.y, s, b4.w), 0.f);
        float* orow = g_h1 + (size_t)node * 64 + seg * 8;
        *(float4*)orow = o0;
        *(float4*)(orow + 4) = o1;
    }
}

// warp per node, 16 edges per unrolled iter: lane = group(3b)*4 + seg(2b); fused gemm3
__global__ void __launch_bounds__(256, 6) k_agg32g3(const float* __restrict__ b,
                                                    const float* __restrict__ W3) {
    int node = (blockIdx.x * blockDim.x + threadIdx.x) >> 5;
    if (node >= NN) return;
    int lane = threadIdx.x & 31;
    int g = lane >> 2;       // edge group 0-7
    int seg = lane & 3;      // feature segment (8 features = 16B)
    int deg = g_cnt[node];
    const int* bp = g_bkt + (size_t)node * BKT;
    __half2 a0 = __float2half2_rn(0.f), a1 = a0, a2 = a0, a3 = a0;
    for (int j = 0; j < deg; j += 16) {
        int e0 = j + g, e1 = j + 8 + g;
        bool q0 = e0 < deg, q1 = e1 < deg;
        int c0 = __ldg(bp + min(e0, deg - 1));
        int c1 = __ldg(bp + min(e1, deg - 1));
        uint4 va = *(const uint4*)(g_t2h + (size_t)c0 * 32 + seg * 8);
        uint4 vb = *(const uint4*)(g_t2h + (size_t)c1 * 32 + seg * 8);
        if (q0) {
            a0 = __hadd2(a0, u2h2(va.x));
            a1 = __hadd2(a1, u2h2(va.y));
            a2 = __hadd2(a2, u2h2(va.z));
            a3 = __hadd2(a3, u2h2(va.w));
        }
        if (q1) {
            a0 = __hadd2(a0, u2h2(vb.x));
            a1 = __hadd2(a1, u2h2(vb.y));
            a2 = __hadd2(a2, u2h2(vb.z));
            a3 = __hadd2(a3, u2h2(vb.w));
        }
    }
    // reduce across the 8 edge groups (lanes xor 4, 8, 16)
#pragma unroll
    for (int off = 4; off <= 16; off <<= 1) {
        a0 = __hadd2(a0, shflx_h2(a0, off));
        a1 = __hadd2(a1, shflx_h2(a1, off));
        a2 = __hadd2(a2, shflx_h2(a2, off));
        a3 = __hadd2(a3, shflx_h2(a3, off));
    }
    // every lane holds full sums for its seg; h2 + gemm3 partials
    float s = rsqrtf((float)deg);
    float2 f0 = __half22float2(a0), f1 = __half22float2(a1);
    float2 f2 = __half22float2(a2), f3 = __half22float2(a3);
    float4 b0 = __ldg((const float4*)(b + seg * 8));
    float4 b4 = __ldg((const float4*)(b + seg * 8 + 4));
    float h[8];
    h[0] = fmaxf(fmaf(f0.x, s, b0.x), 0.f);
    h[1] = fmaxf(fmaf(f0.y, s, b0.y), 0.f);
    h[2] = fmaxf(fmaf(f1.x, s, b0.z), 0.f);
    h[3] = fmaxf(fmaf(f1.y, s, b0.w), 0.f);
    h[4] = fmaxf(fmaf(f2.x, s, b4.x), 0.f);
    h[5] = fmaxf(fmaf(f2.y, s, b4.y), 0.f);
    h[6] = fmaxf(fmaf(f3.x, s, b4.z), 0.f);
    h[7] = fmaxf(fmaf(f3.y, s, b4.w), 0.f);
    float p0 = 0.f, p1 = 0.f;
#pragma unroll
    for (int i = 0; i < 8; i++) {
        float2 wv = __ldg((const float2*)(W3 + 2 * (seg * 8 + i)));
        p0 = fmaf(h[i], wv.x, p0);
        p1 = fmaf(h[i], wv.y, p1);
    }
#pragma unroll
    for (int off = 1; off <= 2; off <<= 1) {
        p0 += __shfl_xor_sync(0xffffffffu, p0, off);
        p1 += __shfl_xor_sync(0xffffffffu, p1, off);
    }
    if (lane == 0)
        *(float2*)(g_t3 + 2 * (size_t)node) = make_float2(p0 * s, p1 * s);
}

// warp per node, lane-strided edges: out = log_softmax(dinv[d] * sum + b3)
__global__ void __launch_bounds__(256, 6) k_aggout(const float* __restrict__ b,
                                                   float* __restrict__ out) {
    int node = (blockIdx.x * blockDim.x + threadIdx.x) >> 5;
    if (node >= NN) return;
    int lane = threadIdx.x & 31;
    int deg = g_cnt[node];
    const int* bp = g_bkt + (size_t)node * BKT;
    float a0 = 0.f, a1 = 0.f;
    for (int j = lane; j < deg; j += 32) {
        int c = __ldg(bp + j);
        float2 v = *(const float2*)(g_t3 + 2 * (size_t)c);
        a0 += v.x;
        a1 += v.y;
    }
#pragma unroll
    for (int off = 16; off > 0; off >>= 1) {
        a0 += __shfl_xor_sync(0xffffffffu, a0, off);
        a1 += __shfl_xor_sync(0xffffffffu, a1, off);
    }
    if (lane == 0) {
        float s = rsqrtf((float)deg);
        a0 = a0 * s + __ldg(&b[0]);
        a1 = a1 * s + __ldg(&b[1]);
        float m = fmaxf(a0, a1);
        float l = m + log1pf(expf(-fabsf(a0 - a1)));
        *(float2*)(out + 2 * (size_t)node) = make_float2(a0 - l, a1 - l);
    }
}

// ---------------- launch ----------------

extern "C" void kernel_launch(void* const* d_in, const int* in_sizes, int n_in,
                              void* d_out, int out_size) {
    const float* x  = (const float*)d_in[0];
    const int*   ei = (const int*)d_in[1];    // int32 (JAX x64 disabled)
    const float* W1 = (const float*)d_in[2];
    const float* b1 = (const float*)d_in[3];
    const float* W2 = (const float*)d_in[4];
    const float* b2 = (const float*)d_in[5];
    const float* W3 = (const float*)d_in[6];
    const float* b3 = (const float*)d_in[7];
    float* out = (float*)d_out;

    static cudaStream_t sGemm = nullptr;
    static cudaEvent_t evFork = nullptr, evJoin = nullptr;
    if (sGemm == nullptr) {
        cudaStreamCreateWithFlags(&sGemm, cudaStreamNonBlocking);
        cudaEventCreateWithFlags(&evFork, cudaEventDisableTiming);
        cudaEventCreateWithFlags(&evJoin, cudaEventDisableTiming);
    }

    const int TB = 256;
    const int nB  = (NN + TB - 1) / TB;           // 391
    const int e4B = (EE / 4 + TB - 1) / TB;       // 3125
    const int wB  = (NN * 32 + TB - 1) / TB;      // 12500 warp-per-node

    // fork: gemm1 (launch #1) runs concurrently with bucket build
    cudaEventRecord(evFork, 0);
    cudaStreamWaitEvent(sGemm, evFork, 0);
    k_gemm1<<<NN / 32, TB, 0, sGemm>>>(x, W1);    // #1 (side stream)
    cudaEventRecord(evJoin, sGemm);

    // bucket CSR build (single atomic pass)
    k_initbkt<<<nB, TB>>>();                      // #2
    k_scatter<<<e4B, TB>>>(ei);                   // #3

    // join: agg64 needs gemm1 output + buckets
    cudaStreamWaitEvent(0, evJoin, 0);
    k_agg64<<<wB, TB>>>(b1);                      // #4  <- profiled

    // layer 2 dense
    k_gemm2<<<(NN + 63) / 64, TB>>>(W2);          // #5

    // layer 2 aggregate + layer 3 dense (fused)
    k_agg32g3<<<wB, TB>>>(b2, W3);                // #6

    // layer 3 aggregate + log_softmax
    k_aggout<<<wB, TB>>>(b3, out);                // #7
}

// round 14
// speedup vs baseline: 1.0435x; 1.0435x over previous
#include <cuda_runtime.h>
#include <cuda_fp16.h>
#include <math.h>

#define NN 100000
#define EE 3200000
#define BKT 128                  // bucket capacity per node (P(overflow) ~ 1e-30)

typedef unsigned long long ull_t;

// ---- static device scratch (no dynamic allocation allowed) ----
__device__ int    g_cnt[NN];                 // cursor, ends as degree (incl self-loop)
__device__ int    g_bkt[(size_t)NN * BKT];   // column indices, 512B-aligned rows
__device__ __half g_xwh[(size_t)NN * 64];    // UNscaled fp16 gather table, layer1
__device__ float  g_h1[(size_t)NN * 64];
__device__ __half g_t2h[(size_t)NN * 32];    // dinv-scaled fp16 gather table, layer2
__device__ float  g_t3[(size_t)NN * 2];      // dinv-scaled layer3 pre-agg (fp32)

// ---- packed f32x2 helpers (two independent fp32 FMAs) ----
__device__ __forceinline__ void ffma2(ull_t& acc, ull_t a, ull_t b) {
    asm("fma.rn.f32x2 %0, %1, %2, %0;" : "+l"(acc) : "l"(a), "l"(b));
}
__device__ __forceinline__ ull_t fdup(float v) {
    ull_t d;
    asm("mov.b64 %0, {%1, %1};" : "=l"(d) : "f"(v));
    return d;
}
__device__ __forceinline__ float2 funpack(ull_t v) {
    float2 r;
    asm("mov.b64 {%0, %1}, %2;" : "=f"(r.x), "=f"(r.y) : "l"(v));
    return r;
}
__device__ __forceinline__ __half2 shflx_h2(__half2 v, int off) {
    unsigned u = *(unsigned*)&v;
    u = __shfl_xor_sync(0xffffffffu, u, off);
    return *(__half2*)&u;
}
__device__ __forceinline__ __half2 u2h2(unsigned u) { return *(__half2*)&u; }

// ---------------- bucket CSR build (single atomic pass) ----------------

__global__ void k_initbkt() {
    int i = blockIdx.x * blockDim.x + threadIdx.x;
    if (i >= NN) return;
    g_cnt[i] = 1;
    g_bkt[(size_t)i * BKT] = i;   // self-loop at slot 0
}

// 4 edges per thread, int4 src/dst reads (EE % 4 == 0)
__global__ void k_scatter(const int* __restrict__ ei) {
    int t = blockIdx.x * blockDim.x + threadIdx.x;
    if (t >= EE / 4) return;
    int4 s = ((const int4*)ei)[t];
    int4 d = ((const int4*)(ei + EE))[t];
    int p0 = atomicAdd(&g_cnt[d.x], 1);
    if (p0 < BKT) g_bkt[(size_t)d.x * BKT + p0] = s.x;
    int p1 = atomicAdd(&g_cnt[d.y], 1);
    if (p1 < BKT) g_bkt[(size_t)d.y * BKT + p1] = s.y;
    int p2 = atomicAdd(&g_cnt[d.z], 1);
    if (p2 < BKT) g_bkt[(size_t)d.z * BKT + p2] = s.z;
    int p3 = atomicAdd(&g_cnt[d.w], 1);
    if (p3 < BKT) g_bkt[(size_t)d.w * BKT + p3] = s.w;
}

// ---------------- dense GEMMs (f32x2 packed FFMA) ----------------

// x[NN,128] @ W1[128,64] -> g_xwh (fp16, UNscaled); 32 rows/block
__global__ void k_gemm1(const float* __restrict__ x, const float* __restrict__ W) {
    __shared__ float Ws[128 * 64];     // 32 KB
    __shared__ ull_t xd[32][128];      // 32 KB: duplicated {x,x}
    int tid = threadIdx.x;
    for (int i = tid; i < 2048; i += 256)
        ((float4*)Ws)[i] = ((const float4*)W)[i];
    int row0 = blockIdx.x * 32;
    for (int i = tid; i < 1024; i += 256) {
        int r = i >> 5, c = i & 31;
        float4 v = ((const float4*)(x + (size_t)(row0 + r) * 128))[c];
        xd[r][c * 4 + 0] = fdup(v.x);
        xd[r][c * 4 + 1] = fdup(v.y);
        xd[r][c * 4 + 2] = fdup(v.z);
        xd[r][c * 4 + 3] = fdup(v.w);
    }
    __syncthreads();
    int tx = tid & 15, ty = tid >> 4;
    ull_t a00 = 0, a01 = 0, a10 = 0, a11 = 0;
#pragma unroll 8
    for (int k = 0; k < 128; k++) {
        ulonglong2 w = ((const ulonglong2*)(Ws + k * 64))[tx];
        ull_t xa = xd[ty][k], xb = xd[ty + 16][k];
        ffma2(a00, xa, w.x); ffma2(a01, xa, w.y);
        ffma2(a10, xb, w.x); ffma2(a11, xb, w.y);
    }
    {
        float2 p0 = funpack(a00), p1 = funpack(a01);
        __half2 h0 = __floats2half2_rn(p0.x, p0.y);
        __half2 h1 = __floats2half2_rn(p1.x, p1.y);
        uint2 u; u.x = *(unsigned*)&h0; u.y = *(unsigned*)&h1;
        *(uint2*)(g_xwh + (size_t)(row0 + ty) * 64 + tx * 4) = u;
    }
    {
        float2 p0 = funpack(a10), p1 = funpack(a11);
        __half2 h0 = __floats2half2_rn(p0.x, p0.y);
        __half2 h1 = __floats2half2_rn(p1.x, p1.y);
        uint2 u; u.x = *(unsigned*)&h0; u.y = *(unsigned*)&h1;
        *(uint2*)(g_xwh + (size_t)(row0 + ty + 16) * 64 + tx * 4) = u;
    }
}

// g_h1[NN,64] @ W2[64,32] * dinv[row] -> g_t2h (fp16) ; 64 rows/block
__global__ void k_gemm2(const float* __restrict__ W) {
    __shared__ float Ws[64 * 32];
    __shared__ ull_t xd[64][64];
    int tid = threadIdx.x;
    for (int i = tid; i < 512; i += 256)
        ((float4*)Ws)[i] = ((const float4*)W)[i];
    int row0 = blockIdx.x * 64;
    for (int i = tid; i < 1024; i += 256) {
        int r = i >> 4, c = i & 15;
        int gr = row0 + r;
        float4 v = (gr < NN) ? ((const float4*)(g_h1 + (size_t)gr * 64))[c]
                             : make_float4(0, 0, 0, 0);
        xd[r][c * 4 + 0] = fdup(v.x);
        xd[r][c * 4 + 1] = fdup(v.y);
        xd[r][c * 4 + 2] = fdup(v.z);
        xd[r][c * 4 + 3] = fdup(v.w);
    }
    __syncthreads();
    int tx = tid & 7, ty = tid >> 3;
    ull_t a00 = 0, a01 = 0, a10 = 0, a11 = 0;
#pragma unroll 8
    for (int k = 0; k < 64; k++) {
        ulonglong2 w = ((const ulonglong2*)(Ws + k * 32))[tx];
        ull_t xa = xd[ty][k], xb = xd[ty + 32][k];
        ffma2(a00, xa, w.x); ffma2(a01, xa, w.y);
        ffma2(a10, xb, w.x); ffma2(a11, xb, w.y);
    }
    int r0 = row0 + ty, r1 = row0 + ty + 32;
    if (r0 < NN) {
        float s = rsqrtf((float)g_cnt[r0]);
        float2 p0 = funpack(a00), p1 = funpack(a01);
        __half2 h0 = __floats2half2_rn(p0.x * s, p0.y * s);
        __half2 h1 = __floats2half2_rn(p1.x * s, p1.y * s);
        uint2 u; u.x = *(unsigned*)&h0; u.y = *(unsigned*)&h1;
        *(uint2*)(g_t2h + (size_t)r0 * 32 + tx * 4) = u;
    }
    if (r1 < NN) {
        float s = rsqrtf((float)g_cnt[r1]);
        float2 p0 = funpack(a10), p1 = funpack(a11);
        __half2 h0 = __floats2half2_rn(p0.x * s, p0.y * s);
        __half2 h1 = __floats2half2_rn(p1.x * s, p1.y * s);
        uint2 u; u.x = *(unsigned*)&h0; u.y = *(unsigned*)&h1;
        *(uint2*)(g_t2h + (size_t)r1 * 32 + tx * 4) = u;
    }
}

// ---------------- bucket aggregations ----------------

// warp per node, 8 edges per unrolled iter: lane = group(2b)*8 + seg(3b)
__global__ void __launch_bounds__(256, 6) k_agg64(const float* __restrict__ b) {
    int node = (blockIdx.x * blockDim.x + threadIdx.x) >> 5;
    if (node >= NN) return;
    int lane = threadIdx.x & 31;
    int g = lane >> 3;       // edge group 0-3
    int seg = lane & 7;      // feature segment (8 features = 16B)
    int deg = g_cnt[node];
    const int* bp = g_bkt + (size_t)node * BKT;
    const __half* tab = g_xwh;
    __half2 a0 = __float2half2_rn(0.f), a1 = a0, a2 = a0, a3 = a0;
    for (int j = 0; j < deg; j += 8) {
        // hoist both index loads -> two independent gather chains in flight
        int e0 = j + g, e1 = j + 4 + g;
        bool q0 = e0 < deg, q1 = e1 < deg;
        int c0 = __ldg(bp + min(e0, deg - 1));
        int c1 = __ldg(bp + min(e1, deg - 1));
        float w0f = q0 ? rsqrtf((float)__ldg(&g_cnt[c0])) : 0.f;
        float w1f = q1 ? rsqrtf((float)__ldg(&g_cnt[c1])) : 0.f;
        uint4 va = *(const uint4*)(tab + (size_t)c0 * 64 + seg * 8);
        uint4 vb = *(const uint4*)(tab + (size_t)c1 * 64 + seg * 8);
        __half2 w0 = __float2half2_rn(w0f);
        __half2 w1 = __float2half2_rn(w1f);
        a0 = __hfma2(w0, u2h2(va.x), a0);
        a1 = __hfma2(w0, u2h2(va.y), a1);
        a2 = __hfma2(w0, u2h2(va.z), a2);
        a3 = __hfma2(w0, u2h2(va.w), a3);
        a0 = __hfma2(w1, u2h2(vb.x), a0);
        a1 = __hfma2(w1, u2h2(vb.y), a1);
        a2 = __hfma2(w1, u2h2(vb.z), a2);
        a3 = __hfma2(w1, u2h2(vb.w), a3);
    }
    // reduce across the 4 edge groups (lanes xor 8, 16)
#pragma unroll
    for (int off = 8; off <= 16; off <<= 1) {
        a0 = __hadd2(a0, shflx_h2(a0, off));
        a1 = __hadd2(a1, shflx_h2(a1, off));
        a2 = __hadd2(a2, shflx_h2(a2, off));
        a3 = __hadd2(a3, shflx_h2(a3, off));
    }
    if (lane < 8) {     // seg == lane
        float s = rsqrtf((float)deg);
        float2 f0 = __half22float2(a0), f1 = __half22float2(a1);
        float2 f2 = __half22float2(a2), f3 = __half22float2(a3);
        float4 b0 = __ldg((const float4*)(b + seg * 8));
        float4 b4 = __ldg((const float4*)(b + seg * 8 + 4));
        float4 o0, o1;
        o0.x = fmaxf(fmaf(f0.x, s, b0.x), 0.f);
        o0.y = fmaxf(fmaf(f0.y, s, b0.y), 0.f);
        o0.z = fmaxf(fmaf(f1.x, s, b0.z), 0.f);
        o0.w = fmaxf(fmaf(f1.y, s, b0.w), 0.f);
        o1.x = fmaxf(fmaf(f2.x, s, b4.x), 0.f);
        o1.y = fmaxf(fmaf(f2.y, s, b4.y), 0.f);
        o1.z = fmaxf(fmaf(f3.x, s, b4.z), 0.f);
        o1.w = fmaxf(fmaf(f3.y, s, b4.w), 0.f);
        float* orow = g_h1 + (size_t)node * 64 + seg * 8;
        *(float4*)orow = o0;
        *(float4*)(orow + 4) = o1;
    }
}

// warp per node, 8 edges/iteration: lane = group(3b)*4 + seg(2b); fused gemm3
__global__ void k_agg32g3(const float* __restrict__ b, const float* __restrict__ W3) {
    int node = (blockIdx.x * blockDim.x + threadIdx.x) >> 5;
    if (node >= NN) return;
    int lane = threadIdx.x & 31;
    int g = lane >> 2;       // edge group 0-7
    int seg = lane & 3;      // feature segment (8 features = 16B)
    int deg = g_cnt[node];
    const int* bp = g_bkt + (size_t)node * BKT;
    __half2 a0 = __float2half2_rn(0.f), a1 = a0, a2 = a0, a3 = a0;
    for (int j = 0; j < deg; j += 8) {
        int e = j + g;
        bool valid = e < deg;
        e = min(e, deg - 1);
        int c = __ldg(bp + e);
        uint4 v = *(const uint4*)(g_t2h + (size_t)c * 32 + seg * 8);
        if (valid) {
            a0 = __hadd2(a0, u2h2(v.x));
            a1 = __hadd2(a1, u2h2(v.y));
            a2 = __hadd2(a2, u2h2(v.z));
            a3 = __hadd2(a3, u2h2(v.w));
        }
    }
    // reduce across the 8 edge groups (lanes xor 4, 8, 16)
#pragma unroll
    for (int off = 4; off <= 16; off <<= 1) {
        a0 = __hadd2(a0, shflx_h2(a0, off));
        a1 = __hadd2(a1, shflx_h2(a1, off));
        a2 = __hadd2(a2, shflx_h2(a2, off));
        a3 = __hadd2(a3, shflx_h2(a3, off));
    }
    // every lane now holds the full sums for its seg; compute h2 + gemm3 partials
    float s = rsqrtf((float)deg);
    float2 f0 = __half22float2(a0), f1 = __half22float2(a1);
    float2 f2 = __half22float2(a2), f3 = __half22float2(a3);
    float4 b0 = __ldg((const float4*)(b + seg * 8));
    float4 b4 = __ldg((const float4*)(b + seg * 8 + 4));
    float h[8];
    h[0] = fmaxf(fmaf(f0.x, s, b0.x), 0.f);
    h[1] = fmaxf(fmaf(f0.y, s, b0.y), 0.f);
    h[2] = fmaxf(fmaf(f1.x, s, b0.z), 0.f);
    h[3] = fmaxf(fmaf(f1.y, s, b0.w), 0.f);
    h[4] = fmaxf(fmaf(f2.x, s, b4.x), 0.f);
    h[5] = fmaxf(fmaf(f2.y, s, b4.y), 0.f);
    h[6] = fmaxf(fmaf(f3.x, s, b4.z), 0.f);
    h[7] = fmaxf(fmaf(f3.y, s, b4.w), 0.f);
    float p0 = 0.f, p1 = 0.f;
#pragma unroll
    for (int i = 0; i < 8; i++) {
        float2 wv = __ldg((const float2*)(W3 + 2 * (seg * 8 + i)));
        p0 = fmaf(h[i], wv.x, p0);
        p1 = fmaf(h[i], wv.y, p1);
    }
#pragma unroll
    for (int off = 1; off <= 2; off <<= 1) {
        p0 += __shfl_xor_sync(0xffffffffu, p0, off);
        p1 += __shfl_xor_sync(0xffffffffu, p1, off);
    }
    if (lane == 0)
        *(float2*)(g_t3 + 2 * (size_t)node) = make_float2(p0 * s, p1 * s);
}

// thread per node, 2 features: out = log_softmax(dinv[d] * sum + b3)
__global__ void k_aggout(const float* __restrict__ b, float* __restrict__ out) {
    int i = blockIdx.x * blockDim.x + threadIdx.x;
    if (i >= NN) return;
    int deg = g_cnt[i];
    const int* bp = g_bkt + (size_t)i * BKT;
    float a0 = 0.f, a1 = 0.f;
    int j = 0;
    for (; j + 4 <= deg; j += 4) {
        int4 c = *(const int4*)(bp + j);
        float2 v0 = *(const float2*)(g_t3 + 2 * (size_t)c.x);
        float2 v1 = *(const float2*)(g_t3 + 2 * (size_t)c.y);
        float2 v2 = *(const float2*)(g_t3 + 2 * (size_t)c.z);
        float2 v3 = *(const float2*)(g_t3 + 2 * (size_t)c.w);
        a0 += v0.x + v1.x + v2.x + v3.x;
        a1 += v0.y + v1.y + v2.y + v3.y;
    }
    for (; j < deg; j++) {
        int c = __ldg(bp + j);
        float2 v = *(const float2*)(g_t3 + 2 * (size_t)c);
        a0 += v.x;
        a1 += v.y;
    }
    float s = rsqrtf((float)deg);
    a0 = a0 * s + __ldg(&b[0]);
    a1 = a1 * s + __ldg(&b[1]);
    float m = fmaxf(a0, a1);
    float l = m + log1pf(expf(-fabsf(a0 - a1)));
    out[2 * i]     = a0 - l;
    out[2 * i + 1] = a1 - l;
}

// ---------------- launch ----------------

extern "C" void kernel_launch(void* const* d_in, const int* in_sizes, int n_in,
                              void* d_out, int out_size) {
    const float* x  = (const float*)d_in[0];
    const int*   ei = (const int*)d_in[1];    // int32 (JAX x64 disabled)
    const float* W1 = (const float*)d_in[2];
    const float* b1 = (const float*)d_in[3];
    const float* W2 = (const float*)d_in[4];
    const float* b2 = (const float*)d_in[5];
    const float* W3 = (const float*)d_in[6];
    const float* b3 = (const float*)d_in[7];
    float* out = (float*)d_out;

    static cudaStream_t sGemm = nullptr;
    static cudaEvent_t evFork = nullptr, evJoin = nullptr;
    if (sGemm == nullptr) {
        cudaStreamCreateWithFlags(&sGemm, cudaStreamNonBlocking);
        cudaEventCreateWithFlags(&evFork, cudaEventDisableTiming);
        cudaEventCreateWithFlags(&evJoin, cudaEventDisableTiming);
    }

    const int TB = 256;
    const int nB  = (NN + TB - 1) / TB;           // 391
    const int e4B = (EE / 4 + TB - 1) / TB;       // 3125
    const int wB  = (NN * 32 + TB - 1) / TB;      // 12500 warp-per-node

    // fork: gemm1 (launch #1) runs concurrently with bucket build
    cudaEventRecord(evFork, 0);
    cudaStreamWaitEvent(sGemm, evFork, 0);
    k_gemm1<<<NN / 32, TB, 0, sGemm>>>(x, W1);    // #1 (side stream)
    cudaEventRecord(evJoin, sGemm);

    // bucket CSR build (single atomic pass)
    k_initbkt<<<nB, TB>>>();                      // #2
    k_scatter<<<e4B, TB>>>(ei);                   // #3

    // join: agg64 needs gemm1 output + buckets
    cudaStreamWaitEvent(0, evJoin, 0);
    k_agg64<<<wB, TB>>>(b1);                      // #4  <- profiled

    // layer 2 dense
    k_gemm2<<<(NN + 63) / 64, TB>>>(W2);          // #5

    // layer 2 aggregate + layer 3 dense (fused)
    k_agg32g3<<<wB, TB>>>(b2, W3);                // #6

    // layer 3 aggregate + log_softmax
    k_aggout<<<nB, TB>>>(b3, out);                // #7
}